// round 14
// baseline (speedup 1.0000x reference)
#include <cuda_runtime.h>
#include <cstdint>
#include <cstddef>

#define B_   128
#define T_   512
#define H_   256
#define G4_  1024

// recurrence geometry: 8 independent groups x 32 CTAs, 16 rows/group, 8 h-cols/CTA
#define NG       8
#define GRP_CTAS 32
#define HSTR     258           // hs2 row stride in u64 (even, padded)
// smem: Us2 [256k][8j] ulonglong2 = 32KB | hs2 u64[16][258] = 33KB | P [16p][16r][8j] ulonglong2 = 32KB
#define OFF_HS   32768
#define OFF_P    (OFF_HS + 16*HSTR*8)
#define REC_SMEM (OFF_P + 16*16*8*16)

// ---------------- scratch (device globals; no allocation allowed) ----------------
__device__ float g_xz[(size_t)B_ * T_ * G4_];    // gate pre-activations (reused per layer)
__device__ float g_hseq[(size_t)B_ * T_ * H_];   // per-layer hidden sequence (also h-exchange)
__device__ unsigned long long g_arrive[NG * 16];     // padded per-group counters
__device__ unsigned long long g_release[NG * 16];

// ---------------- packed f32x2 helpers (sm_103a FFMA2) ----------------
static __device__ __forceinline__ unsigned long long f2pack(float a, float b) {
    unsigned long long r;
    asm("mov.b64 %0, {%1, %2};" : "=l"(r) : "r"(__float_as_uint(a)), "r"(__float_as_uint(b)));
    return r;
}
static __device__ __forceinline__ void f2unpack(unsigned long long v, float& a, float& b) {
    unsigned int x, y;
    asm("mov.b64 {%0, %1}, %2;" : "=r"(x), "=r"(y) : "l"(v));
    a = __uint_as_float(x); b = __uint_as_float(y);
}
static __device__ __forceinline__ unsigned long long f2fma(
    unsigned long long a, unsigned long long b, unsigned long long c) {
    unsigned long long d;
    asm("fma.rn.f32x2 %0, %1, %2, %3;" : "=l"(d) : "l"(a), "l"(b), "l"(c));
    return d;
}
static __device__ __forceinline__ unsigned long long f2add(
    unsigned long long a, unsigned long long b) {
    unsigned long long d;
    asm("add.rn.f32x2 %0, %1, %2;" : "=l"(d) : "l"(a), "l"(b));
    return d;
}

// fast activations (rel err ~1e-6; tolerance 1e-3)
static __device__ __forceinline__ float sig_f(float x) {
    return __fdividef(1.f, 1.f + __expf(-x));
}
static __device__ __forceinline__ float tanh_f(float x) {
    return __fdividef(2.f, 1.f + __expf(-2.f * x)) - 1.f;
}

// ---------------- per-group barrier (32 CTAs; groups independent) ----------------
static __device__ __forceinline__ void gsync(int grp, unsigned long long& phase) {
    __threadfence();
    __syncthreads();
    if (threadIdx.x == 0) {
        unsigned long long old = atomicAdd(&g_arrive[grp * 16], 1ULL);
        if (old == phase * GRP_CTAS + (GRP_CTAS - 1)) {
            __threadfence();
            *(volatile unsigned long long*)&g_release[grp * 16] = phase + 1;
        } else {
            while (*(volatile unsigned long long*)&g_release[grp * 16] <= phase) { }
        }
        phase++;
    }
    __syncthreads();
}

// ---------------- GEMM: C[M,N] = A[M,256] @ Bw[256,N] + bias (+tanh) ----------------
template <bool TANH>
__global__ __launch_bounds__(256, 2) void gemm_bias(
    const float* __restrict__ A, const float* __restrict__ Bw,
    const float* __restrict__ bias, float* __restrict__ C, int N)
{
    __shared__ unsigned long long As2[16][130];
    __shared__ float Bs[16][132];
    const int tid = threadIdx.x;
    const int m0 = blockIdx.y * 128;
    const int n0 = blockIdx.x * 128;
    const int tr = tid >> 4;
    const int tc = tid & 15;

    unsigned long long acc[8][4];
#pragma unroll
    for (int i = 0; i < 8; i++)
#pragma unroll
        for (int p = 0; p < 4; p++) acc[i][p] = 0ULL;

    for (int k0 = 0; k0 < 256; k0 += 16) {
#pragma unroll
        for (int s = 0; s < 2; s++) {
            int e = tid + s * 256;
            int row = e >> 2, q = e & 3;
            float4 v = *(const float4*)&A[(size_t)(m0 + row) * 256 + k0 + q * 4];
            As2[q * 4 + 0][row] = f2pack(v.x, v.x);
            As2[q * 4 + 1][row] = f2pack(v.y, v.y);
            As2[q * 4 + 2][row] = f2pack(v.z, v.z);
            As2[q * 4 + 3][row] = f2pack(v.w, v.w);
        }
#pragma unroll
        for (int s = 0; s < 2; s++) {
            int e = tid + s * 256;
            int krow = e >> 5, nq = e & 31;
            *(float4*)&Bs[krow][nq * 4] =
                *(const float4*)&Bw[(size_t)(k0 + krow) * N + n0 + nq * 4];
        }
        __syncthreads();
#pragma unroll
        for (int kk = 0; kk < 16; kk++) {
            ulonglong2 a0 = *(const ulonglong2*)&As2[kk][tr * 8 + 0];
            ulonglong2 a1 = *(const ulonglong2*)&As2[kk][tr * 8 + 2];
            ulonglong2 a2 = *(const ulonglong2*)&As2[kk][tr * 8 + 4];
            ulonglong2 a3 = *(const ulonglong2*)&As2[kk][tr * 8 + 6];
            ulonglong2 b0 = *(const ulonglong2*)&Bs[kk][tc * 8 + 0];
            ulonglong2 b1 = *(const ulonglong2*)&Bs[kk][tc * 8 + 4];
            unsigned long long ap[8] = {a0.x, a0.y, a1.x, a1.y, a2.x, a2.y, a3.x, a3.y};
            unsigned long long bp[4] = {b0.x, b0.y, b1.x, b1.y};
#pragma unroll
            for (int i = 0; i < 8; i++)
#pragma unroll
                for (int p = 0; p < 4; p++)
                    acc[i][p] = f2fma(ap[i], bp[p], acc[i][p]);
        }
        __syncthreads();
    }

    float4 bv0 = *(const float4*)&bias[n0 + tc * 8];
    float4 bv1 = *(const float4*)&bias[n0 + tc * 8 + 4];
#pragma unroll
    for (int i = 0; i < 8; i++) {
        float c0, c1, c2, c3, c4, c5, c6, c7;
        f2unpack(acc[i][0], c0, c1);
        f2unpack(acc[i][1], c2, c3);
        f2unpack(acc[i][2], c4, c5);
        f2unpack(acc[i][3], c6, c7);
        c0 += bv0.x; c1 += bv0.y; c2 += bv0.z; c3 += bv0.w;
        c4 += bv1.x; c5 += bv1.y; c6 += bv1.z; c7 += bv1.w;
        if (TANH) {
            c0 = tanh_f(c0); c1 = tanh_f(c1); c2 = tanh_f(c2); c3 = tanh_f(c3);
            c4 = tanh_f(c4); c5 = tanh_f(c5); c6 = tanh_f(c6); c7 = tanh_f(c7);
        }
        float* cp = &C[(size_t)(m0 + tr * 8 + i) * N + n0 + tc * 8];
        *(float4*)cp = make_float4(c0, c1, c2, c3);
        *(float4*)(cp + 4) = make_float4(c4, c5, c6, c7);
    }
}

// ---------------- persistent LSTM recurrence (v11: 16-row blocking + 2 CTAs/SM) ----------------
// 256 CTAs; 8 groups x 32 CTAs; group = 16 batch rows, CTA = 8 h-cols.
// Thread = (j, 8-k chunk), accumulates ALL 16 rows (U quad read once, reused 16x).
// ~98KB smem + <=128 regs -> 2 co-resident CTAs (different groups) per SM hide each
// other's barrier/refill/reduction phases.
__global__ __launch_bounds__(256, 2) void lstm_rec(
    const float* __restrict__ xz, const float* __restrict__ U, float* __restrict__ hseq)
{
    extern __shared__ unsigned char sraw[];
    ulonglong2* Us2 = (ulonglong2*)sraw;                             // [256 k][8 j]
    unsigned long long* hs2 = (unsigned long long*)(sraw + OFF_HS);  // [16 r][HSTR] (h,h)
    ulonglong2* P = (ulonglong2*)(sraw + OFF_P);                     // [16 p][16 r][8 j]

    const int tid = threadIdx.x;
    const int cta = blockIdx.x;
    const int grp = cta >> 5;            // 0..7
    const int slot = cta & 31;
    const int r0 = grp * 16;             // batch rows
    const int j0 = slot * 8;             // h columns
    const int wid = tid >> 5;            // 0..7
    const int lane = tid & 31;
    const int kc = tid >> 3;             // k-chunk 0..31 (8 k each)
    const int j = tid & 7;               // 0..7
    const int kbase = kc * 8;
    // reduction-phase cell assignment (threads 0..127)
    const int rr = tid >> 3;             // row 0..15
    const int jj = tid & 7;              // col 0..7

    // Load U slice once: Us2[k*8+j] = {(U[k][i],U[k][f]), (U[k][g],U[k][o])}
    for (int e = tid; e < 2048; e += 256) {
        int k = e >> 3, jx = e & 7;
        const float* up = U + (size_t)k * G4_ + j0 + jx;
        ulonglong2 v;
        v.x = f2pack(up[0], up[256]);
        v.y = f2pack(up[512], up[768]);
        Us2[e] = v;
    }
    // Zero duplicated h tile (h(-1) = 0)
    for (int e = tid; e < 16 * HSTR; e += 256) hs2[e] = 0ULL;

    unsigned long long phase = 0;
    if (tid == 0) phase = *(volatile unsigned long long*)&g_release[grp * 16];

    // Prime xz for t=0 (cell (rr,jj), threads < 128)
    float cz0 = 0.f, cz1 = 0.f, cz2 = 0.f, cz3 = 0.f;
    if (tid < 128) {
        const float* xp = xz + (size_t)(r0 + rr) * T_ * G4_ + j0 + jj;
        cz0 = __ldcs(xp);
        cz1 = __ldcs(xp + 256);
        cz2 = __ldcs(xp + 512);
        cz3 = __ldcs(xp + 768);
    }
    float c = 0.f;
    __syncthreads();

    const ulonglong2* up2 = Us2 + (size_t)kbase * 8 + j;      // index [kk*8]
    const unsigned long long* hb = hs2 + kbase;               // index [r*HSTR + kk]

    for (int t = 0; t < T_; ++t) {
        // Prefetch next step's xz (consumed after reduction, far away)
        float nz0 = 0.f, nz1 = 0.f, nz2 = 0.f, nz3 = 0.f;
        if (tid < 128 && t + 1 < T_) {
            const float* xp = xz + ((size_t)(r0 + rr) * T_ + (t + 1)) * G4_ + j0 + jj;
            nz0 = __ldcs(xp);
            nz1 = __ldcs(xp + 256);
            nz2 = __ldcs(xp + 512);
            nz3 = __ldcs(xp + 768);
        }

        // FMA: 8 k x 16 rows; one U-quad read per k, reused across all 16 rows
        unsigned long long accA[16], accB[16];
#pragma unroll
        for (int r = 0; r < 16; r++) { accA[r] = 0ULL; accB[r] = 0ULL; }
#pragma unroll
        for (int kk = 0; kk < 8; kk += 2) {
            ulonglong2 u0 = up2[(size_t)kk * 8];
            ulonglong2 u1 = up2[(size_t)(kk + 1) * 8];
#pragma unroll
            for (int r = 0; r < 16; r++) {
                ulonglong2 h2 = *(const ulonglong2*)&hb[(size_t)r * HSTR + kk];  // bcast/8 lanes
                accA[r] = f2fma(h2.x, u0.x, accA[r]);
                accB[r] = f2fma(h2.x, u0.y, accB[r]);
                accA[r] = f2fma(h2.y, u1.x, accA[r]);
                accB[r] = f2fma(h2.y, u1.y, accB[r]);
            }
        }

        // Stage 1: fold kc-pairs (lane, lane+16) via one u64 shuffle stage
#pragma unroll
        for (int r = 0; r < 16; r++) {
            accA[r] = f2add(accA[r], __shfl_down_sync(0xFFFFFFFFu, accA[r], 16));
            accB[r] = f2add(accB[r], __shfl_down_sync(0xFFFFFFFFu, accB[r], 16));
        }
        // Stage 2: 16 partial sets to smem (lanes 0..15 of each warp)
        if (lane < 16) {
            int p = wid * 2 + (lane >> 3);       // 0..15
            ulonglong2* pw = P + (size_t)p * 128 + (lane & 7);
#pragma unroll
            for (int r = 0; r < 16; r++)
                pw[(size_t)r * 8] = make_ulonglong2(accA[r], accB[r]);
        }
        __syncthreads();

        // Stage 3: cell (rr,jj) sums its 16 partials, applies gates
        if (tid < 128) {
            unsigned long long zA = 0ULL, zB = 0ULL;
#pragma unroll
            for (int pv = 0; pv < 16; pv++) {
                ulonglong2 p = P[(size_t)pv * 128 + rr * 8 + jj];
                zA = f2add(zA, p.x);
                zB = f2add(zB, p.y);
            }
            float azi, azf, azg, azo;
            f2unpack(zA, azi, azf);
            f2unpack(zB, azg, azo);
            azi += cz0; azf += cz1; azg += cz2; azo += cz3;
            float ig = sig_f(azi);
            float fg = sig_f(azf);
            float gg = tanh_f(azg);
            float og = sig_f(azo);
            c = fg * c + ig * gg;
            float h = og * tanh_f(c);
            __stcg(&hseq[((size_t)(r0 + rr) * T_ + t) * H_ + j0 + jj], h);
        }
        cz0 = nz0; cz1 = nz1; cz2 = nz2; cz3 = nz3;

        gsync(grp, phase);   // h(t) visible group-wide

        // Refill duplicated h tile from L2-hot hseq[t]
        if (t + 1 < T_) {
#pragma unroll
            for (int i = 0; i < 4; i++) {
                int e = tid + i * 256;
                int rw = e >> 6, cc = (e & 63) * 4;
                float4 v = __ldcg((const float4*)&hseq[((size_t)(r0 + rw) * T_ + t) * H_ + cc]);
                unsigned long long* d = hs2 + (size_t)rw * HSTR + cc;
                d[0] = f2pack(v.x, v.x);
                d[1] = f2pack(v.y, v.y);
                d[2] = f2pack(v.z, v.z);
                d[3] = f2pack(v.w, v.w);
            }
            __syncthreads();
        }
    }
}

// ---------------- LayerNorm over last dim (256), one warp per row ----------------
__global__ __launch_bounds__(256) void ln_kernel(
    const float* __restrict__ X, const float* __restrict__ gamma,
    const float* __restrict__ beta, float* __restrict__ out)
{
    int w = threadIdx.x >> 5, lane = threadIdx.x & 31;
    size_t row = (size_t)blockIdx.x * 8 + w;
    const float* x = X + row * 256;
    float4 v0 = *(const float4*)&x[lane * 4];
    float4 v1 = *(const float4*)&x[128 + lane * 4];
    float s = v0.x + v0.y + v0.z + v0.w + v1.x + v1.y + v1.z + v1.w;
    float q = v0.x * v0.x + v0.y * v0.y + v0.z * v0.z + v0.w * v0.w
            + v1.x * v1.x + v1.y * v1.y + v1.z * v1.z + v1.w * v1.w;
#pragma unroll
    for (int o = 16; o > 0; o >>= 1) {
        s += __shfl_xor_sync(0xFFFFFFFFu, s, o);
        q += __shfl_xor_sync(0xFFFFFFFFu, q, o);
    }
    float mu = s * (1.f / 256.f);
    float var = q * (1.f / 256.f) - mu * mu;
    float rstd = rsqrtf(var + 1e-3f);
    float4 g0 = *(const float4*)&gamma[lane * 4];
    float4 g1 = *(const float4*)&gamma[128 + lane * 4];
    float4 e0 = *(const float4*)&beta[lane * 4];
    float4 e1 = *(const float4*)&beta[128 + lane * 4];
    float4 o0, o1;
    o0.x = (v0.x - mu) * rstd * g0.x + e0.x;
    o0.y = (v0.y - mu) * rstd * g0.y + e0.y;
    o0.z = (v0.z - mu) * rstd * g0.z + e0.z;
    o0.w = (v0.w - mu) * rstd * g0.w + e0.w;
    o1.x = (v1.x - mu) * rstd * g1.x + e1.x;
    o1.y = (v1.y - mu) * rstd * g1.y + e1.y;
    o1.z = (v1.z - mu) * rstd * g1.z + e1.z;
    o1.w = (v1.w - mu) * rstd * g1.w + e1.w;
    float* op = out + row * 256;
    *(float4*)&op[lane * 4] = o0;
    *(float4*)&op[128 + lane * 4] = o1;
}

// ---------------- entry point ----------------
extern "C" void kernel_launch(void* const* d_in, const int* in_sizes, int n_in,
                              void* d_out, int out_size)
{
    const float* x  = (const float*)d_in[0];
    const float* W0 = (const float*)d_in[1];
    const float* U0 = (const float*)d_in[2];
    const float* b0 = (const float*)d_in[3];
    const float* W1 = (const float*)d_in[4];
    const float* U1 = (const float*)d_in[5];
    const float* b1 = (const float*)d_in[6];
    const float* Wd = (const float*)d_in[7];
    const float* bd = (const float*)d_in[8];
    const float* ga = (const float*)d_in[9];
    const float* be = (const float*)d_in[10];
    float* out = (float*)d_out;

    float *xz, *hseq;
    cudaGetSymbolAddress((void**)&xz, g_xz);
    cudaGetSymbolAddress((void**)&hseq, g_hseq);
    cudaFuncSetAttribute(lstm_rec, cudaFuncAttributeMaxDynamicSharedMemorySize, REC_SMEM);

    // Layer 0
    gemm_bias<false><<<dim3(8, 512), 256>>>(x, W0, b0, xz, G4_);
    lstm_rec<<<256, 256, REC_SMEM>>>(xz, U0, hseq);
    // Layer 1
    gemm_bias<false><<<dim3(8, 512), 256>>>(hseq, W1, b1, xz, G4_);
    lstm_rec<<<256, 256, REC_SMEM>>>(xz, U1, hseq);
    // Dense + tanh (into g_xz scratch), then LayerNorm
    gemm_bias<true><<<dim3(2, 512), 256>>>(hseq, Wd, bd, xz, H_);
    ln_kernel<<<8192, 256>>>(xz, ga, be, out);
}

// round 15
// speedup vs baseline: 1.0585x; 1.0585x over previous
#include <cuda_runtime.h>
#include <cstdint>
#include <cstddef>

#define B_   128
#define T_   512
#define H_   256
#define G4_  1024

// recurrence geometry: 8 independent groups x 16 CTAs, 16 rows/group, 16 h-cols/CTA
#define NG       8
#define GRP_CTAS 16
#define HSTR     258
// smem: Us2 [256k][16j] ulonglong2 = 64KB | hs2 u64[16][258] = 32.25KB | P [8w][8r][16j] u128 = 16KB | base
#define OFF_HS   65536
#define OFF_P    (OFF_HS + 16*HSTR*8)
#define OFF_BASE (OFF_P + 8*8*16*16)
#define REC_SMEM (OFF_BASE + 16)

// ---------------- scratch (device globals; no allocation allowed) ----------------
__device__ float g_xz[(size_t)B_ * T_ * G4_];    // gate pre-activations (reused per layer)
__device__ float g_hseq[(size_t)B_ * T_ * H_];   // hidden sequence (layer0 then layer1; flag-ordered aliasing)
__device__ unsigned long long g_arrive[NG * 16];     // padded per-group counters
__device__ unsigned long long g_release[NG * 16];
__device__ unsigned int g_tileflag[4096];        // per-GEMM-tile monotonic flags (shared by both layers)

// ---------------- packed f32x2 helpers (sm_103a FFMA2) ----------------
static __device__ __forceinline__ unsigned long long f2pack(float a, float b) {
    unsigned long long r;
    asm("mov.b64 %0, {%1, %2};" : "=l"(r) : "r"(__float_as_uint(a)), "r"(__float_as_uint(b)));
    return r;
}
static __device__ __forceinline__ void f2unpack(unsigned long long v, float& a, float& b) {
    unsigned int x, y;
    asm("mov.b64 {%0, %1}, %2;" : "=r"(x), "=r"(y) : "l"(v));
    a = __uint_as_float(x); b = __uint_as_float(y);
}
static __device__ __forceinline__ unsigned long long f2fma(
    unsigned long long a, unsigned long long b, unsigned long long c) {
    unsigned long long d;
    asm("fma.rn.f32x2 %0, %1, %2, %3;" : "=l"(d) : "l"(a), "l"(b), "l"(c));
    return d;
}
static __device__ __forceinline__ unsigned long long f2add(
    unsigned long long a, unsigned long long b) {
    unsigned long long d;
    asm("add.rn.f32x2 %0, %1, %2;" : "=l"(d) : "l"(a), "l"(b));
    return d;
}

// fast activations (rel err ~1e-6; tolerance 1e-3)
static __device__ __forceinline__ float sig_f(float x) {
    return __fdividef(1.f, 1.f + __expf(-x));
}
static __device__ __forceinline__ float tanh_f(float x) {
    return __fdividef(2.f, 1.f + __expf(-2.f * x)) - 1.f;
}

// ---------------- per-group barrier (16 CTAs; groups independent) ----------------
static __device__ __forceinline__ void gsync(int grp, unsigned long long& phase) {
    __threadfence();
    __syncthreads();
    if (threadIdx.x == 0) {
        unsigned long long old = atomicAdd(&g_arrive[grp * 16], 1ULL);
        if (old == phase * GRP_CTAS + (GRP_CTAS - 1)) {
            __threadfence();
            *(volatile unsigned long long*)&g_release[grp * 16] = phase + 1;
        } else {
            while (*(volatile unsigned long long*)&g_release[grp * 16] <= phase) { }
        }
        phase++;
    }
    __syncthreads();
}

// ================= fused layer: 128 recurrence CTAs + 4096 chasing GEMM CTAs =================
// GEMM part: xz[m,1024] = A[m,256] @ W[256,1024] + b for m = r*512+t, tiles 128x128,
// tile id G = tb*1024 + r*8 + nb (t-block-major so early t completes first); flags G.
// Rec part: R13 16-row register-blocked recurrence; waits tile flags at t-block boundaries.
__global__ __launch_bounds__(256, 2) void fused_layer(
    const float* __restrict__ A, const float* __restrict__ W, const float* __restrict__ bias,
    const float* __restrict__ U, float* __restrict__ xz, float* __restrict__ hseq)
{
    extern __shared__ unsigned char sraw[];
    const int tid = threadIdx.x;

    if (blockIdx.x >= 128) {
        // ---------------- GEMM tile CTA ----------------
        unsigned long long (*As2)[130] = (unsigned long long (*)[130])sraw;     // [16][130]
        float (*Bs)[132] = (float (*)[132])(sraw + 16 * 130 * 8);               // [16][132]
        const int g2 = blockIdx.x - 128;
        const int nb = g2 & 7;
        const int rm = (g2 >> 3) & 127;
        const int tb = g2 >> 10;
        const int m0 = rm * 512 + tb * 128;
        const int n0 = nb * 128;
        const int tr = tid >> 4;
        const int tc = tid & 15;

        unsigned long long acc[8][4];
#pragma unroll
        for (int i = 0; i < 8; i++)
#pragma unroll
            for (int p = 0; p < 4; p++) acc[i][p] = 0ULL;

        for (int k0 = 0; k0 < 256; k0 += 16) {
#pragma unroll
            for (int s = 0; s < 2; s++) {
                int e = tid + s * 256;
                int row = e >> 2, q = e & 3;
                float4 v = *(const float4*)&A[(size_t)(m0 + row) * 256 + k0 + q * 4];
                As2[q * 4 + 0][row] = f2pack(v.x, v.x);
                As2[q * 4 + 1][row] = f2pack(v.y, v.y);
                As2[q * 4 + 2][row] = f2pack(v.z, v.z);
                As2[q * 4 + 3][row] = f2pack(v.w, v.w);
            }
#pragma unroll
            for (int s = 0; s < 2; s++) {
                int e = tid + s * 256;
                int krow = e >> 5, nq = e & 31;
                *(float4*)&Bs[krow][nq * 4] =
                    *(const float4*)&W[(size_t)(k0 + krow) * G4_ + n0 + nq * 4];
            }
            __syncthreads();
#pragma unroll
            for (int kk = 0; kk < 16; kk++) {
                ulonglong2 a0 = *(const ulonglong2*)&As2[kk][tr * 8 + 0];
                ulonglong2 a1 = *(const ulonglong2*)&As2[kk][tr * 8 + 2];
                ulonglong2 a2 = *(const ulonglong2*)&As2[kk][tr * 8 + 4];
                ulonglong2 a3 = *(const ulonglong2*)&As2[kk][tr * 8 + 6];
                ulonglong2 b0 = *(const ulonglong2*)&Bs[kk][tc * 8 + 0];
                ulonglong2 b1 = *(const ulonglong2*)&Bs[kk][tc * 8 + 4];
                unsigned long long ap[8] = {a0.x, a0.y, a1.x, a1.y, a2.x, a2.y, a3.x, a3.y};
                unsigned long long bp[4] = {b0.x, b0.y, b1.x, b1.y};
#pragma unroll
                for (int i = 0; i < 8; i++)
#pragma unroll
                    for (int p = 0; p < 4; p++)
                        acc[i][p] = f2fma(ap[i], bp[p], acc[i][p]);
            }
            __syncthreads();
        }

        float4 bv0 = *(const float4*)&bias[n0 + tc * 8];
        float4 bv1 = *(const float4*)&bias[n0 + tc * 8 + 4];
#pragma unroll
        for (int i = 0; i < 8; i++) {
            float c0, c1, c2, c3, c4, c5, c6, c7;
            f2unpack(acc[i][0], c0, c1);
            f2unpack(acc[i][1], c2, c3);
            f2unpack(acc[i][2], c4, c5);
            f2unpack(acc[i][3], c6, c7);
            c0 += bv0.x; c1 += bv0.y; c2 += bv0.z; c3 += bv0.w;
            c4 += bv1.x; c5 += bv1.y; c6 += bv1.z; c7 += bv1.w;
            float* cp = &xz[(size_t)(m0 + tr * 8 + i) * G4_ + n0 + tc * 8];
            *(float4*)cp = make_float4(c0, c1, c2, c3);
            *(float4*)(cp + 4) = make_float4(c4, c5, c6, c7);
        }
        __threadfence();
        __syncthreads();
        if (tid == 0) atomicAdd(&g_tileflag[g2], 1u);
        return;
    }

    // ---------------- recurrence CTA (R13 core + tile-flag chasing + two-pass P) ----------------
    ulonglong2* Us2 = (ulonglong2*)sraw;                             // [256 k][16 j]
    unsigned long long* hs2 = (unsigned long long*)(sraw + OFF_HS);  // [16 r][HSTR] (h,h)
    ulonglong2* P = (ulonglong2*)(sraw + OFF_P);                     // [8 w][8 r][16 j]
    unsigned int* sbase = (unsigned int*)(sraw + OFF_BASE);

    const int cta = blockIdx.x;
    const int grp = cta >> 4;            // 0..7
    const int slot = cta & 15;
    const int r0 = grp * 16;             // batch rows
    const int j0 = slot * 16;            // h columns
    const int wid = tid >> 5;
    const int lane = tid & 31;
    const int kbase = (tid >> 4) * 16;   // k-chunk base
    const int j = tid & 15;
    const int rr = tid >> 4;             // cell row 0..15
    const int jj = tid & 15;             // cell col 0..15

    // Load U slice once: Us2[k*16+j] = {(U[k][i],U[k][f]), (U[k][g],U[k][o])}
    for (int e = tid; e < 4096; e += 256) {
        int k = e >> 4, jx = e & 15;
        const float* up = U + (size_t)k * G4_ + j0 + jx;
        ulonglong2 v;
        v.x = f2pack(up[0], up[256]);
        v.y = f2pack(up[512], up[768]);
        Us2[e] = v;
    }
    for (int e = tid; e < 16 * HSTR; e += 256) hs2[e] = 0ULL;

    unsigned long long phase = 0;
    if (tid == 0) {
        phase = *(volatile unsigned long long*)&g_release[grp * 16];
        *sbase = (unsigned int)(phase / (unsigned long long)T_ + 1ULL);  // tile-flag target
    }
    __syncthreads();
    const unsigned int ftgt = *sbase;

    // wait for t-block 0 tiles of our 16 rows (128 flags, one per thread<128)
    {
        if (tid < 128) {
            const volatile unsigned int* fp = &g_tileflag[(r0 + (tid >> 3)) * 8 + (tid & 7)];
            while (*fp < ftgt) { }
            __threadfence();
        }
        __syncthreads();
    }

    // Prime xz for t=0
    float cz0, cz1, cz2, cz3;
    {
        const float* xp = xz + (size_t)(r0 + rr) * T_ * G4_ + j0 + jj;
        cz0 = __ldcs(xp);
        cz1 = __ldcs(xp + 256);
        cz2 = __ldcs(xp + 512);
        cz3 = __ldcs(xp + 768);
    }
    float c = 0.f;
    __syncthreads();

    const ulonglong2* up2 = Us2 + (size_t)kbase * 16 + j;
    const unsigned long long* hb = hs2 + kbase;

    for (int t = 0; t < T_; ++t) {
        // chase: before prefetching t+1, ensure its t-block tiles are published
        if (((t + 1) & 127) == 0 && t + 1 < T_) {
            int tb = (t + 1) >> 7;
            if (tid < 128) {
                const volatile unsigned int* fp =
                    &g_tileflag[tb * 1024 + (r0 + (tid >> 3)) * 8 + (tid & 7)];
                while (*fp < ftgt) { }
                __threadfence();
            }
            __syncthreads();
        }
        // Prefetch next step's xz
        float nz0 = 0.f, nz1 = 0.f, nz2 = 0.f, nz3 = 0.f;
        if (t + 1 < T_) {
            const float* xp = xz + ((size_t)(r0 + rr) * T_ + (t + 1)) * G4_ + j0 + jj;
            nz0 = __ldcs(xp);
            nz1 = __ldcs(xp + 256);
            nz2 = __ldcs(xp + 512);
            nz3 = __ldcs(xp + 768);
        }

        // FMA: 16 k x 16 rows; one U-quad read per k, reused across all 16 rows
        unsigned long long accA[16], accB[16];
#pragma unroll
        for (int r = 0; r < 16; r++) { accA[r] = 0ULL; accB[r] = 0ULL; }
#pragma unroll
        for (int kk = 0; kk < 16; kk += 2) {
            ulonglong2 u0 = up2[(size_t)kk * 16];
            ulonglong2 u1 = up2[(size_t)(kk + 1) * 16];
#pragma unroll
            for (int r = 0; r < 16; r++) {
                ulonglong2 h2 = *(const ulonglong2*)&hb[(size_t)r * HSTR + kk];  // broadcast
                accA[r] = f2fma(h2.x, u0.x, accA[r]);
                accB[r] = f2fma(h2.x, u0.y, accB[r]);
                accA[r] = f2fma(h2.y, u1.x, accA[r]);
                accB[r] = f2fma(h2.y, u1.y, accB[r]);
            }
        }
        // Stage 1: fold kc pairs (lane, lane+16)
#pragma unroll
        for (int r = 0; r < 16; r++) {
            accA[r] = f2add(accA[r], __shfl_down_sync(0xFFFFFFFFu, accA[r], 16));
            accB[r] = f2add(accB[r], __shfl_down_sync(0xFFFFFFFFu, accB[r], 16));
        }
        // Two-pass P reduction (halved P buffer)
        unsigned long long zA = 0ULL, zB = 0ULL;
        if (lane < 16) {
            ulonglong2* pw = P + (size_t)wid * 128 + lane;
#pragma unroll
            for (int r = 0; r < 8; r++)
                pw[(size_t)r * 16] = make_ulonglong2(accA[r], accB[r]);
        }
        __syncthreads();
        if (tid < 128) {
#pragma unroll
            for (int wv = 0; wv < 8; wv++) {
                ulonglong2 p = P[(size_t)wv * 128 + (rr & 7) * 16 + jj];
                zA = f2add(zA, p.x);
                zB = f2add(zB, p.y);
            }
        }
        __syncthreads();
        if (lane < 16) {
            ulonglong2* pw = P + (size_t)wid * 128 + lane;
#pragma unroll
            for (int r = 8; r < 16; r++)
                pw[(size_t)(r - 8) * 16] = make_ulonglong2(accA[r], accB[r]);
        }
        __syncthreads();
        if (tid >= 128) {
#pragma unroll
            for (int wv = 0; wv < 8; wv++) {
                ulonglong2 p = P[(size_t)wv * 128 + (rr & 7) * 16 + jj];
                zA = f2add(zA, p.x);
                zB = f2add(zB, p.y);
            }
        }
        // gates for cell (rr, jj)
        {
            float azi, azf, azg, azo;
            f2unpack(zA, azi, azf);
            f2unpack(zB, azg, azo);
            azi += cz0; azf += cz1; azg += cz2; azo += cz3;
            float ig = sig_f(azi);
            float fg = sig_f(azf);
            float gg = tanh_f(azg);
            float og = sig_f(azo);
            c = fg * c + ig * gg;
            float h = og * tanh_f(c);
            __stcg(&hseq[((size_t)(r0 + rr) * T_ + t) * H_ + j0 + jj], h);
        }
        cz0 = nz0; cz1 = nz1; cz2 = nz2; cz3 = nz3;

        gsync(grp, phase);   // h(t) visible group-wide

        // Refill duplicated h tile from L2-hot hseq[t]
        if (t + 1 < T_) {
#pragma unroll
            for (int i = 0; i < 4; i++) {
                int e = tid + i * 256;
                int rw = e >> 6, cc = (e & 63) * 4;
                float4 v = __ldcg((const float4*)&hseq[((size_t)(r0 + rw) * T_ + t) * H_ + cc]);
                unsigned long long* d = hs2 + (size_t)rw * HSTR + cc;
                d[0] = f2pack(v.x, v.x);
                d[1] = f2pack(v.y, v.y);
                d[2] = f2pack(v.z, v.z);
                d[3] = f2pack(v.w, v.w);
            }
            __syncthreads();
        }
    }
}

// ---------------- dense GEMM (N=256) + tanh, static smem (separate kernel) ----------------
__global__ __launch_bounds__(256, 2) void gemm_dense(
    const float* __restrict__ A, const float* __restrict__ Bw,
    const float* __restrict__ bias, float* __restrict__ C)
{
    __shared__ unsigned long long As2[16][130];
    __shared__ float Bs[16][132];
    const int tid = threadIdx.x;
    const int m0 = blockIdx.y * 128;
    const int n0 = blockIdx.x * 128;
    const int tr = tid >> 4;
    const int tc = tid & 15;

    unsigned long long acc[8][4];
#pragma unroll
    for (int i = 0; i < 8; i++)
#pragma unroll
        for (int p = 0; p < 4; p++) acc[i][p] = 0ULL;

    for (int k0 = 0; k0 < 256; k0 += 16) {
#pragma unroll
        for (int s = 0; s < 2; s++) {
            int e = tid + s * 256;
            int row = e >> 2, q = e & 3;
            float4 v = *(const float4*)&A[(size_t)(m0 + row) * 256 + k0 + q * 4];
            As2[q * 4 + 0][row] = f2pack(v.x, v.x);
            As2[q * 4 + 1][row] = f2pack(v.y, v.y);
            As2[q * 4 + 2][row] = f2pack(v.z, v.z);
            As2[q * 4 + 3][row] = f2pack(v.w, v.w);
        }
#pragma unroll
        for (int s = 0; s < 2; s++) {
            int e = tid + s * 256;
            int krow = e >> 5, nq = e & 31;
            *(float4*)&Bs[krow][nq * 4] =
                *(const float4*)&Bw[(size_t)(k0 + krow) * H_ + n0 + nq * 4];
        }
        __syncthreads();
#pragma unroll
        for (int kk = 0; kk < 16; kk++) {
            ulonglong2 a0 = *(const ulonglong2*)&As2[kk][tr * 8 + 0];
            ulonglong2 a1 = *(const ulonglong2*)&As2[kk][tr * 8 + 2];
            ulonglong2 a2 = *(const ulonglong2*)&As2[kk][tr * 8 + 4];
            ulonglong2 a3 = *(const ulonglong2*)&As2[kk][tr * 8 + 6];
            ulonglong2 b0 = *(const ulonglong2*)&Bs[kk][tc * 8 + 0];
            ulonglong2 b1 = *(const ulonglong2*)&Bs[kk][tc * 8 + 4];
            unsigned long long ap[8] = {a0.x, a0.y, a1.x, a1.y, a2.x, a2.y, a3.x, a3.y};
            unsigned long long bp[4] = {b0.x, b0.y, b1.x, b1.y};
#pragma unroll
            for (int i = 0; i < 8; i++)
#pragma unroll
                for (int p = 0; p < 4; p++)
                    acc[i][p] = f2fma(ap[i], bp[p], acc[i][p]);
        }
        __syncthreads();
    }

    float4 bv0 = *(const float4*)&bias[n0 + tc * 8];
    float4 bv1 = *(const float4*)&bias[n0 + tc * 8 + 4];
#pragma unroll
    for (int i = 0; i < 8; i++) {
        float c0, c1, c2, c3, c4, c5, c6, c7;
        f2unpack(acc[i][0], c0, c1);
        f2unpack(acc[i][1], c2, c3);
        f2unpack(acc[i][2], c4, c5);
        f2unpack(acc[i][3], c6, c7);
        c0 = tanh_f(c0 + bv0.x); c1 = tanh_f(c1 + bv0.y);
        c2 = tanh_f(c2 + bv0.z); c3 = tanh_f(c3 + bv0.w);
        c4 = tanh_f(c4 + bv1.x); c5 = tanh_f(c5 + bv1.y);
        c6 = tanh_f(c6 + bv1.z); c7 = tanh_f(c7 + bv1.w);
        float* cp = &C[(size_t)(m0 + tr * 8 + i) * H_ + n0 + tc * 8];
        *(float4*)cp = make_float4(c0, c1, c2, c3);
        *(float4*)(cp + 4) = make_float4(c4, c5, c6, c7);
    }
}

// ---------------- LayerNorm over last dim (256), one warp per row ----------------
__global__ __launch_bounds__(256) void ln_kernel(
    const float* __restrict__ X, const float* __restrict__ gamma,
    const float* __restrict__ beta, float* __restrict__ out)
{
    int w = threadIdx.x >> 5, lane = threadIdx.x & 31;
    size_t row = (size_t)blockIdx.x * 8 + w;
    const float* x = X + row * 256;
    float4 v0 = *(const float4*)&x[lane * 4];
    float4 v1 = *(const float4*)&x[128 + lane * 4];
    float s = v0.x + v0.y + v0.z + v0.w + v1.x + v1.y + v1.z + v1.w;
    float q = v0.x * v0.x + v0.y * v0.y + v0.z * v0.z + v0.w * v0.w
            + v1.x * v1.x + v1.y * v1.y + v1.z * v1.z + v1.w * v1.w;
#pragma unroll
    for (int o = 16; o > 0; o >>= 1) {
        s += __shfl_xor_sync(0xFFFFFFFFu, s, o);
        q += __shfl_xor_sync(0xFFFFFFFFu, q, o);
    }
    float mu = s * (1.f / 256.f);
    float var = q * (1.f / 256.f) - mu * mu;
    float rstd = rsqrtf(var + 1e-3f);
    float4 g0 = *(const float4*)&gamma[lane * 4];
    float4 g1 = *(const float4*)&gamma[128 + lane * 4];
    float4 e0 = *(const float4*)&beta[lane * 4];
    float4 e1 = *(const float4*)&beta[128 + lane * 4];
    float4 o0, o1;
    o0.x = (v0.x - mu) * rstd * g0.x + e0.x;
    o0.y = (v0.y - mu) * rstd * g0.y + e0.y;
    o0.z = (v0.z - mu) * rstd * g0.z + e0.z;
    o0.w = (v0.w - mu) * rstd * g0.w + e0.w;
    o1.x = (v1.x - mu) * rstd * g1.x + e1.x;
    o1.y = (v1.y - mu) * rstd * g1.y + e1.y;
    o1.z = (v1.z - mu) * rstd * g1.z + e1.z;
    o1.w = (v1.w - mu) * rstd * g1.w + e1.w;
    float* op = out + row * 256;
    *(float4*)&op[lane * 4] = o0;
    *(float4*)&op[128 + lane * 4] = o1;
}

// ---------------- entry point ----------------
extern "C" void kernel_launch(void* const* d_in, const int* in_sizes, int n_in,
                              void* d_out, int out_size)
{
    const float* x  = (const float*)d_in[0];
    const float* W0 = (const float*)d_in[1];
    const float* U0 = (const float*)d_in[2];
    const float* b0 = (const float*)d_in[3];
    const float* W1 = (const float*)d_in[4];
    const float* U1 = (const float*)d_in[5];
    const float* b1 = (const float*)d_in[6];
    const float* Wd = (const float*)d_in[7];
    const float* bd = (const float*)d_in[8];
    const float* ga = (const float*)d_in[9];
    const float* be = (const float*)d_in[10];
    float* out = (float*)d_out;

    float *xz, *hseq;
    cudaGetSymbolAddress((void**)&xz, g_xz);
    cudaGetSymbolAddress((void**)&hseq, g_hseq);
    cudaFuncSetAttribute(fused_layer, cudaFuncAttributeMaxDynamicSharedMemorySize, REC_SMEM);

    // Layer 0: GEMM chases into recurrence within one kernel
    fused_layer<<<128 + 4096, 256, REC_SMEM>>>(x, W0, b0, U0, xz, hseq);
    // Layer 1: same; GEMM reads h0 from hseq (flag-ordered before h1 overwrites)
    fused_layer<<<128 + 4096, 256, REC_SMEM>>>(hseq, W1, b1, U1, xz, hseq);
    // Dense + tanh (into g_xz scratch), then LayerNorm
    gemm_dense<<<dim3(2, 512), 256>>>(hseq, Wd, bd, xz);
    ln_kernel<<<8192, 256>>>(xz, ga, be, out);
}